// round 16
// baseline (speedup 1.0000x reference)
#include <cuda_runtime.h>

typedef unsigned long long u64;

#define B_    16384
#define N_    128
#define DIR_  16
#define KGEO  18
#define NBLK  2048
#define NTHR  128

__device__ __align__(16) float g_Pre[(size_t)B_ * 64];
__constant__ __align__(16) float cW0geo[KGEO * 64];
__constant__ __align__(16) float cW1[64 * 64];

// ---------- packed f32x2 helpers (FFMA2 path, PTX-only) ----------
static __device__ __forceinline__ u64 ffma2(u64 a, u64 b, u64 c) {
    u64 d;
    asm("fma.rn.f32x2 %0, %1, %2, %3;" : "=l"(d) : "l"(a), "l"(b), "l"(c));
    return d;
}
static __device__ __forceinline__ u64 pack2(float x) {
    u64 r; unsigned xi = __float_as_uint(x);
    asm("mov.b64 %0, {%1, %1};" : "=l"(r) : "r"(xi));
    return r;
}
static __device__ __forceinline__ u64 pack2f(float a, float b) {
    u64 r;
    asm("mov.b64 %0, {%1, %2};" : "=l"(r)
        : "r"(__float_as_uint(a)), "r"(__float_as_uint(b)));
    return r;
}
static __device__ __forceinline__ void unpack2(u64 v, float& a, float& b) {
    unsigned lo, hi;
    asm("mov.b64 {%0, %1}, %2;" : "=r"(lo), "=r"(hi) : "l"(v));
    a = __uint_as_float(lo); b = __uint_as_float(hi);
}
static __device__ __forceinline__ unsigned smem_u32(const void* p) {
    unsigned a;
    asm("{ .reg .u64 t; cvta.to.shared.u64 t, %1; cvt.u32.u64 %0, t; }"
        : "=r"(a) : "l"(p));
    return a;
}
static __device__ __forceinline__ void cp_async16(unsigned s, const void* g) {
    asm volatile("cp.async.ca.shared.global [%0], [%1], 16;"
                 :: "r"(s), "l"(g) : "memory");
}

// One k-step of the 2p x 32c tile against a weight row (smem or const pointer)
#define KSTEP(ACTBASE, KIDX, WROW) do {                                       \
    u64 av = *(const u64*)((ACTBASE) + (KIDX) * 128 + p0);                    \
    float a0f, a1f; unpack2(av, a0f, a1f);                                    \
    u64 a0 = pack2(a0f), a1 = pack2(a1f);                                     \
    const ulonglong2* wr = (const ulonglong2*)(WROW);                         \
    _Pragma("unroll")                                                         \
    for (int jj = 0; jj < 8; jj++) {                                          \
        ulonglong2 w = wr[jj];                                                \
        acc0[2 * jj]     = ffma2(a0, w.x, acc0[2 * jj]);                      \
        acc0[2 * jj + 1] = ffma2(a0, w.y, acc0[2 * jj + 1]);                  \
        acc1[2 * jj]     = ffma2(a1, w.x, acc1[2 * jj]);                      \
        acc1[2 * jj + 1] = ffma2(a1, w.y, acc1[2 * jj + 1]);                  \
    }                                                                         \
} while (0)

// ---------------- pre-kernel: g_Pre[row][c] = b0[c] + d[row] @ W0[0:16] --------
__global__ void __launch_bounds__(128)
pre_kernel(const float* __restrict__ dirg,
           const float* __restrict__ W0, const float* __restrict__ b0)
{
    __shared__ float sd[2][DIR_];
    int tid = threadIdx.x;
    int rloc = tid >> 6, c = tid & 63;
    int row = blockIdx.x * 2 + rloc;
    if (tid < 32)
        sd[tid >> 4][tid & 15] = dirg[(size_t)(blockIdx.x * 2 + (tid >> 4)) * DIR_ + (tid & 15)];
    __syncthreads();
    float a = b0[c];
    #pragma unroll
    for (int k = 0; k < DIR_; k++)
        a = fmaf(sd[rloc][k], W0[k * 64 + c], a);
    g_Pre[(size_t)row * 64 + c] = a;
}

// ---------------- main kernel -------------------------------------------------
struct Smem {
    float4 W2q[64];          // (w2c0, w2c1, w2c2, 0)
    float4 PSum[256];        // [point][cg] layer-2 partials
    float  W0geo[KGEO * 64]; // [k][c], geo rows only (even-k path)
    float  W1s[64 * 64];     // [k][c]                 (even-k path)
    float  B1c[64];
    float  B2[4];
    float  PreBuf[64];       // cp.async landing zone for g_Pre row
    float  Max[4];
    float  Sig[N_];
    float  Geo[KGEO * 128];  // [k][point]
    float  Act[64 * 128];    // [c][point], (p0,p1) u64 pairs
    float  CRed[12];
};

__global__ void __launch_bounds__(NTHR, 3)
surfnet_kernel(const int*    __restrict__ x,
               const float4* __restrict__ gw,
               const float*  __restrict__ W0, const float* __restrict__ b0,
               const float*  __restrict__ W1, const float* __restrict__ b1,
               const float*  __restrict__ W2, const float* __restrict__ b2,
               float* __restrict__ outSigma, float* __restrict__ outColor)
{
    extern __shared__ __align__(16) char smem_raw[];
    Smem& S = *reinterpret_cast<Smem*>(smem_raw);

    const int tid  = threadIdx.x;
    const int lane = tid & 31;
    const int warp = tid >> 5;
    // warps {0,1} -> cols 0..31, warps {2,3} -> cols 32..63; thread = 2 points x 32 cols
    const int cg    = warp >> 1;
    const int pairi = ((warp & 1) << 5) | lane;
    const int p0    = pairi * 2;
    const int cbase = cg * 32;

    // ---- stage weights (once per block) ----
    for (int i = tid; i < KGEO * 64; i += NTHR) S.W0geo[i] = W0[(DIR_ + i / 64) * 64 + (i & 63)];
    for (int i = tid; i < 64 * 64; i += NTHR)   S.W1s[i] = W1[i];
    if (tid < 64) {
        S.B1c[tid] = b1[tid];
        S.W2q[tid] = make_float4(W2[tid * 3], W2[tid * 3 + 1], W2[tid * 3 + 2], 0.f);
    }
    if (tid < 3) S.B2[tid] = b2[tid];
    const unsigned preb = smem_u32(S.PreBuf);

    // ---- prologue: prefetch row0 gather + Pre ----
    int row = blockIdx.x;
    const int2* xr0 = ((const int2*)x) + ((size_t)row * N_ + tid) * 3;
    int2 xi0 = xr0[0], xi1 = xr0[1], xi2 = xr0[2];
    float4 f0 = __ldg(gw + xi0.x);
    float4 f1 = __ldg(gw + xi0.y);
    float4 f2 = __ldg(gw + xi1.x);
    float4 f3 = __ldg(gw + xi1.y);
    float4 f4 = __ldg(gw + xi2.x);
    float4 f5 = __ldg(gw + xi2.y);
    if (tid < 16) cp_async16(preb + tid * 16, g_Pre + (size_t)row * 64 + tid * 4);
    asm volatile("cp.async.commit_group;" ::: "memory");
    asm volatile("cp.async.wait_group 0;" ::: "memory");
    __syncthreads();   // weights + PreBuf(row0) published

    for (; row < B_; row += NBLK) {
        // prefetch next row's index words (consumed after [3])
        int rown = row + NBLK; if (rown >= B_) rown = row;
        const int2* xrn = ((const int2*)x) + ((size_t)rown * N_ + tid) * 3;
        int2 nx0 = xrn[0], nx1 = xrn[1], nx2 = xrn[2];

        // ---- phase A: stage Geo from regs (prefetched), sigma ----
        S.Geo[ 0 * 128 + tid] = f0.y; S.Geo[ 1 * 128 + tid] = f0.z; S.Geo[ 2 * 128 + tid] = f0.w;
        S.Geo[ 3 * 128 + tid] = f1.y; S.Geo[ 4 * 128 + tid] = f1.z; S.Geo[ 5 * 128 + tid] = f1.w;
        S.Geo[ 6 * 128 + tid] = f2.y; S.Geo[ 7 * 128 + tid] = f2.z; S.Geo[ 8 * 128 + tid] = f2.w;
        S.Geo[ 9 * 128 + tid] = f3.y; S.Geo[10 * 128 + tid] = f3.z; S.Geo[11 * 128 + tid] = f3.w;
        S.Geo[12 * 128 + tid] = f4.y; S.Geo[13 * 128 + tid] = f4.z; S.Geo[14 * 128 + tid] = f4.w;
        S.Geo[15 * 128 + tid] = f5.y; S.Geo[16 * 128 + tid] = f5.z; S.Geo[17 * 128 + tid] = f5.w;

        float s = fminf(fmaxf(f0.x, 0.f), 1.f);
        s *= fminf(fmaxf(f1.x, 0.f), 1.f);
        s *= fminf(fmaxf(f2.x, 0.f), 1.f);
        s *= fminf(fmaxf(f3.x, 0.f), 1.f);
        s *= fminf(fmaxf(f4.x, 0.f), 1.f);
        s *= fminf(fmaxf(f5.x, 0.f), 1.f);
        float sigma0 = s + 1e-4f;

        float m = sigma0;
        #pragma unroll
        for (int o = 16; o > 0; o >>= 1)
            m = fmaxf(m, __shfl_xor_sync(0xffffffffu, m, o));
        if (lane == 0) S.Max[warp] = m;
        __syncthreads();  // [1] Geo, Max ready

        float rowmax = fmaxf(fmaxf(S.Max[0], S.Max[1]), fmaxf(S.Max[2], S.Max[3]));
        float sigma = sigma0 / rowmax;
        S.Sig[tid] = sigma;
        outSigma[(size_t)row * N_ + tid] = sigma;

        // ---- GEMM0: geo(18) -> 64; even k smem, odd k const ----
        u64 acc0[16], acc1[16];
        {
            const u64* pre = (const u64*)(S.PreBuf + cbase);
            #pragma unroll
            for (int j = 0; j < 16; j++) { acc0[j] = pre[j]; acc1[j] = pre[j]; }
        }
        #pragma unroll
        for (int k = 0; k < KGEO; k += 2) {
            KSTEP(S.Geo, k,     S.W0geo + k * 64 + cbase);
            KSTEP(S.Geo, k + 1, cW0geo + (k + 1) * 64 + cbase);
        }
        #pragma unroll
        for (int j = 0; j < 16; j++) {
            float x0, x1, y0, y1;
            unpack2(acc0[j], x0, x1);
            unpack2(acc1[j], y0, y1);
            x0 = fmaxf(x0, 0.f); x1 = fmaxf(x1, 0.f);
            y0 = fmaxf(y0, 0.f); y1 = fmaxf(y1, 0.f);
            int c = cbase + 2 * j;
            *(u64*)(S.Act + c * 128 + p0)       = pack2f(x0, y0);
            *(u64*)(S.Act + (c + 1) * 128 + p0) = pack2f(x1, y1);
        }
        __syncthreads();  // [3] Act ready; Geo + PreBuf fully consumed

        // ---- prefetch next row: gather + Pre row (hidden under GEMM1) ----
        f0 = __ldg(gw + nx0.x);
        f1 = __ldg(gw + nx0.y);
        f2 = __ldg(gw + nx1.x);
        f3 = __ldg(gw + nx1.y);
        f4 = __ldg(gw + nx2.x);
        f5 = __ldg(gw + nx2.y);
        if (tid < 16) cp_async16(preb + tid * 16, g_Pre + (size_t)rown * 64 + tid * 4);
        asm volatile("cp.async.commit_group;" ::: "memory");

        // ---- GEMM1: 64 -> 64; even k smem, odd k const ----
        {
            const u64* bb = (const u64*)(S.B1c + cbase);
            #pragma unroll
            for (int j = 0; j < 16; j++) { acc0[j] = bb[j]; acc1[j] = bb[j]; }
        }
        #pragma unroll 4
        for (int k = 0; k < 64; k += 2) {
            KSTEP(S.Act, k,     S.W1s + k * 64 + cbase);
            KSTEP(S.Act, k + 1, cW1 + (k + 1) * 64 + cbase);
        }

        // ---- layer 2 partials (ReLU fused) ----
        float s0a = 0.f, s1a = 0.f, s2a = 0.f;
        float s0b = 0.f, s1b = 0.f, s2b = 0.f;
        #pragma unroll
        for (int j = 0; j < 16; j++) {
            float x0, x1, y0, y1;
            unpack2(acc0[j], x0, x1);
            unpack2(acc1[j], y0, y1);
            x0 = fmaxf(x0, 0.f); x1 = fmaxf(x1, 0.f);
            y0 = fmaxf(y0, 0.f); y1 = fmaxf(y1, 0.f);
            float4 q0 = S.W2q[cbase + 2 * j];
            float4 q1 = S.W2q[cbase + 2 * j + 1];
            s0a = fmaf(x0, q0.x, s0a); s0a = fmaf(x1, q1.x, s0a);
            s1a = fmaf(x0, q0.y, s1a); s1a = fmaf(x1, q1.y, s1a);
            s2a = fmaf(x0, q0.z, s2a); s2a = fmaf(x1, q1.z, s2a);
            s0b = fmaf(y0, q0.x, s0b); s0b = fmaf(y1, q1.x, s0b);
            s1b = fmaf(y0, q0.y, s1b); s1b = fmaf(y1, q1.y, s1b);
            s2b = fmaf(y0, q0.z, s2b); s2b = fmaf(y1, q1.z, s2b);
        }
        S.PSum[p0 * 2 + cg]       = make_float4(s0a, s1a, s2a, 0.f);
        S.PSum[(p0 + 1) * 2 + cg] = make_float4(s0b, s1b, s2b, 0.f);
        asm volatile("cp.async.wait_group 0;" ::: "memory");
        __syncthreads();  // [4] PSum ready; PreBuf(next) published

        // ---- finish (thread = point) ----
        float4 pa = S.PSum[tid * 2];
        float4 pb = S.PSum[tid * 2 + 1];
        float c0 = pa.x + pb.x + S.B2[0];
        float c1 = pa.y + pb.y + S.B2[1];
        float c2 = pa.z + pb.z + S.B2[2];
        c0 = 1.f / (1.f + __expf(-c0));
        c1 = 1.f / (1.f + __expf(-c1));
        c2 = 1.f / (1.f + __expf(-c2));

        float wgt = (tid == 0 ? 1.f : 1.f - S.Sig[tid - 1]) * sigma;
        float r0 = wgt * c0, r1 = wgt * c1, r2 = wgt * c2;
        #pragma unroll
        for (int o = 16; o > 0; o >>= 1) {
            r0 += __shfl_xor_sync(0xffffffffu, r0, o);
            r1 += __shfl_xor_sync(0xffffffffu, r1, o);
            r2 += __shfl_xor_sync(0xffffffffu, r2, o);
        }
        if (lane == 0) {
            S.CRed[warp * 3 + 0] = r0;
            S.CRed[warp * 3 + 1] = r1;
            S.CRed[warp * 3 + 2] = r2;
        }
        __syncthreads();  // [5] CRed ready; guards Sig/Geo reuse next row
        if (tid == 0) {
            float* oc = outColor + (size_t)row * 3;
            oc[0] = S.CRed[0] + S.CRed[3] + S.CRed[6] + S.CRed[9];
            oc[1] = S.CRed[1] + S.CRed[4] + S.CRed[7] + S.CRed[10];
            oc[2] = S.CRed[2] + S.CRed[5] + S.CRed[8] + S.CRed[11];
        }
    }
}

extern "C" void kernel_launch(void* const* d_in, const int* in_sizes, int n_in,
                              void* d_out, int out_size)
{
    const int*    x    = (const int*)d_in[0];
    const float*  dirg = (const float*)d_in[1];
    const float4* gw   = (const float4*)d_in[2];
    const float*  W0   = (const float*)d_in[3];
    const float*  b0   = (const float*)d_in[4];
    const float*  W1   = (const float*)d_in[5];
    const float*  b1   = (const float*)d_in[6];
    const float*  W2   = (const float*)d_in[7];
    const float*  b2   = (const float*)d_in[8];

    float* outSigma = (float*)d_out;                  // (B, N, 1) flattened
    float* outColor = outSigma + (size_t)B_ * N_;     // (B, 3) flattened

    // mirror weights into constant memory (D2D async copies; graph-capturable)
    cudaMemcpyToSymbolAsync(cW0geo, W0 + DIR_ * 64, KGEO * 64 * sizeof(float),
                            0, cudaMemcpyDeviceToDevice, 0);
    cudaMemcpyToSymbolAsync(cW1, W1, 64 * 64 * sizeof(float),
                            0, cudaMemcpyDeviceToDevice, 0);

    pre_kernel<<<B_ / 2, 128>>>(dirg, W0, b0);

    int smem = (int)sizeof(Smem);
    cudaFuncSetAttribute(surfnet_kernel,
                         cudaFuncAttributeMaxDynamicSharedMemorySize, smem);
    surfnet_kernel<<<NBLK, NTHR, smem>>>(x, gw, W0, b0, W1, b1, W2, b2,
                                         outSigma, outColor);
}